// round 11
// baseline (speedup 1.0000x reference)
#include <cuda_runtime.h>
#include <cuda_fp16.h>
#include <mma.h>

using namespace nvcuda;

#define NMAX 50000
#define EMAX 1600000
#define D 128
#define CAP 128          // slots per row (Poisson(32): P(>128) ~ 0)
#define LDH 136          // padded smem leading dim for fp16 tiles (halves)
#define LDS 132          // padded smem leading dim for fp32 staging (floats)
#define AROWS 64         // A-tile rows per block

// Scratch (static device globals — zero-initialized at module load; the gather
// kernel re-zeroes g_cnt every run, so no memset node is needed)
__device__ int      g_cnt[NMAX];
__device__ unsigned g_edge[(size_t)NMAX * CAP];   // packed: col (lo16) | fp16 val (hi16)
__device__ uint2    g_xwh[(size_t)NMAX * 32];     // XW fp16, row = 32 uint2

__device__ __forceinline__ unsigned pack_edge(int c, float v) {
    return (unsigned)c | ((unsigned)__half_as_ushort(__float2half_rn(v)) << 16);
}

// mixed-precision FMA: f16*f16 + f32 -> f32
__device__ __forceinline__ void edge_fma(unsigned p, int lane, float4& acc) {
    unsigned short c16, v16;
    asm("mov.b32 {%0, %1}, %2;" : "=h"(c16), "=h"(v16) : "r"(p));
    uint2 xu = g_xwh[(size_t)c16 * 32 + lane];
    unsigned short h0, h1, h2, h3;
    asm("mov.b32 {%0, %1}, %2;" : "=h"(h0), "=h"(h1) : "r"(xu.x));
    asm("mov.b32 {%0, %1}, %2;" : "=h"(h2), "=h"(h3) : "r"(xu.y));
    asm("fma.rn.f32.f16 %0, %1, %2, %0;" : "+f"(acc.x) : "h"(v16), "h"(h0));
    asm("fma.rn.f32.f16 %0, %1, %2, %0;" : "+f"(acc.y) : "h"(v16), "h"(h1));
    asm("fma.rn.f32.f16 %0, %1, %2, %0;" : "+f"(acc.z) : "h"(v16), "h"(h2));
    asm("fma.rn.f32.f16 %0, %1, %2, %0;" : "+f"(acc.w) : "h"(v16), "h"(h3));
}

// ---------------------------------------------------------------- scatter, 2 quads (8 chains) per thread
__global__ void k_scatter(const int* __restrict__ row, const int* __restrict__ col,
                          const float* __restrict__ vals, int e) {
    int nq = e >> 2;
    int half = (nq + 1) >> 1;
    int i = blockIdx.x * blockDim.x + threadIdx.x;
    if (i < half) {
        int iB = i + half;
        bool hasB = iB < nq;
        int4   rA = ((const int4*)row)[i];
        int4   cA = ((const int4*)col)[i];
        float4 vA = ((const float4*)vals)[i];
        int4 rB, cB; float4 vB;
        if (hasB) {
            rB = ((const int4*)row)[iB];
            cB = ((const int4*)col)[iB];
            vB = ((const float4*)vals)[iB];
        }
        int pA0 = atomicAdd(&g_cnt[rA.x], 1);
        int pA1 = atomicAdd(&g_cnt[rA.y], 1);
        int pA2 = atomicAdd(&g_cnt[rA.z], 1);
        int pA3 = atomicAdd(&g_cnt[rA.w], 1);
        int pB0 = 0, pB1 = 0, pB2 = 0, pB3 = 0;
        if (hasB) {
            pB0 = atomicAdd(&g_cnt[rB.x], 1);
            pB1 = atomicAdd(&g_cnt[rB.y], 1);
            pB2 = atomicAdd(&g_cnt[rB.z], 1);
            pB3 = atomicAdd(&g_cnt[rB.w], 1);
        }
        if (pA0 < CAP) g_edge[(size_t)rA.x * CAP + pA0] = pack_edge(cA.x, vA.x);
        if (pA1 < CAP) g_edge[(size_t)rA.y * CAP + pA1] = pack_edge(cA.y, vA.y);
        if (pA2 < CAP) g_edge[(size_t)rA.z * CAP + pA2] = pack_edge(cA.z, vA.z);
        if (pA3 < CAP) g_edge[(size_t)rA.w * CAP + pA3] = pack_edge(cA.w, vA.w);
        if (hasB) {
            if (pB0 < CAP) g_edge[(size_t)rB.x * CAP + pB0] = pack_edge(cB.x, vB.x);
            if (pB1 < CAP) g_edge[(size_t)rB.y * CAP + pB1] = pack_edge(cB.y, vB.y);
            if (pB2 < CAP) g_edge[(size_t)rB.z * CAP + pB2] = pack_edge(cB.z, vB.z);
            if (pB3 < CAP) g_edge[(size_t)rB.w * CAP + pB3] = pack_edge(cB.w, vB.w);
        }
    }
    if (i == 0) {
        for (int j = (e >> 2) << 2; j < e; j++) {
            int p = atomicAdd(&g_cnt[row[j]], 1);
            if (p < CAP) g_edge[(size_t)row[j] * CAP + p] = pack_edge(col[j], vals[j]);
        }
    }
}

// ---------------------------------------------------------------- XW = feat @ W (fp16 HMMA, fp32 accum)
// 64x128 tile per block, 256 threads = 8 warps (4x2), warp tile 16x64.
__global__ void __launch_bounds__(256, 3)
k_gemm(const float* __restrict__ feat, const float* __restrict__ w, int n) {
    extern __shared__ __align__(16) char smemraw[];
    __half* Ws = (__half*)smemraw;                    // [128][136] fp16 = 34.8 KB
    __half* As = Ws + 128 * LDH;                      // [64][136]  fp16 = 17.4 KB
    float*  St = (float*)smemraw;                     // fp32 staging [64][132] (reuse)
    int tid = threadIdx.x;

    const float4* w4 = (const float4*)w;
    for (int idx = tid; idx < D * 32; idx += 256) {
        int r = idx >> 5, q = idx & 31;
        float4 v = w4[idx];
        __half2 h0 = __floats2half2_rn(v.x, v.y);
        __half2 h1 = __floats2half2_rn(v.z, v.w);
        *(__half2*)(Ws + r * LDH + q * 4)     = h0;
        *(__half2*)(Ws + r * LDH + q * 4 + 2) = h1;
    }

    int rowBase = blockIdx.x * AROWS;
    const float4* f4 = (const float4*)feat;
    float4 z = make_float4(0.f, 0.f, 0.f, 0.f);
    for (int idx = tid; idx < AROWS * 32; idx += 256) {
        int r = idx >> 5, q = idx & 31;
        int gr = rowBase + r;
        float4 v = (gr < n) ? f4[(size_t)gr * 32 + q] : z;
        __half2 h0 = __floats2half2_rn(v.x, v.y);
        __half2 h1 = __floats2half2_rn(v.z, v.w);
        *(__half2*)(As + r * LDH + q * 4)     = h0;
        *(__half2*)(As + r * LDH + q * 4 + 2) = h1;
    }
    __syncthreads();

    int wid = tid >> 5;
    int wm = wid >> 1;     // 0..3 -> rows wm*16
    int wn = wid & 1;      // 0..1 -> cols wn*64

    wmma::fragment<wmma::accumulator, 16, 16, 16, float> acc[4];
#pragma unroll
    for (int j = 0; j < 4; j++) wmma::fill_fragment(acc[j], 0.f);

#pragma unroll
    for (int k0 = 0; k0 < D; k0 += 16) {
        wmma::fragment<wmma::matrix_a, 16, 16, 16, __half, wmma::row_major> a;
        wmma::fragment<wmma::matrix_b, 16, 16, 16, __half, wmma::row_major> b[4];
        wmma::load_matrix_sync(a, As + (wm * 16) * LDH + k0, LDH);
#pragma unroll
        for (int j = 0; j < 4; j++)
            wmma::load_matrix_sync(b[j], Ws + k0 * LDH + wn * 64 + j * 16, LDH);
#pragma unroll
        for (int j = 0; j < 4; j++)
            wmma::mma_sync(acc[j], a, b[j], acc[j]);
    }
    __syncthreads();   // done with fp16 tiles -> reuse smem as fp32 staging

#pragma unroll
    for (int j = 0; j < 4; j++)
        wmma::store_matrix_sync(St + (wm * 16) * LDS + wn * 64 + j * 16,
                                acc[j], LDS, wmma::mem_row_major);
    __syncthreads();

    for (int idx = tid; idx < AROWS * 32; idx += 256) {
        int r = idx >> 5, q = idx & 31;
        int gr = rowBase + r;
        if (gr < n) {
            float4 v = *(float4*)(St + r * LDS + q * 4);
            __half2 h0 = __floats2half2_rn(v.x, v.y);
            __half2 h1 = __floats2half2_rn(v.z, v.w);
            uint2 u;
            u.x = *reinterpret_cast<unsigned*>(&h0);
            u.y = *reinterpret_cast<unsigned*>(&h1);
            g_xwh[(size_t)gr * 32 + q] = u;
        }
    }
}

// ---------------------------------------------------------------- gather (dual accumulators; re-zeroes g_cnt)
__global__ void k_gather(const float* __restrict__ bias, float* __restrict__ out, int n) {
    int rowid = (blockIdx.x * blockDim.x + threadIdx.x) >> 5;
    int lane = threadIdx.x & 31;
    if (rowid >= n) return;

    int deg = g_cnt[rowid];
    if (lane == 0) g_cnt[rowid] = 0;   // leave counters zeroed for the next launch
    if (deg > CAP) deg = CAP;
    const uint4* eb4 = (const uint4*)&g_edge[(size_t)rowid * CAP];

    float4 acc0 = make_float4(0.f, 0.f, 0.f, 0.f);
    float4 acc1 = make_float4(0.f, 0.f, 0.f, 0.f);

    int j = 0;
    for (; j + 8 <= deg; j += 8) {
        uint4 q0 = eb4[(j >> 2) + 0];
        uint4 q1 = eb4[(j >> 2) + 1];
        edge_fma(q0.x, lane, acc0);
        edge_fma(q0.y, lane, acc1);
        edge_fma(q0.z, lane, acc0);
        edge_fma(q0.w, lane, acc1);
        edge_fma(q1.x, lane, acc0);
        edge_fma(q1.y, lane, acc1);
        edge_fma(q1.z, lane, acc0);
        edge_fma(q1.w, lane, acc1);
    }
    if (j + 4 <= deg) {
        uint4 q0 = eb4[j >> 2];
        edge_fma(q0.x, lane, acc0);
        edge_fma(q0.y, lane, acc1);
        edge_fma(q0.z, lane, acc0);
        edge_fma(q0.w, lane, acc1);
        j += 4;
    }
    const unsigned* eb = &g_edge[(size_t)rowid * CAP];
    for (; j < deg; j++) edge_fma(eb[j], lane, acc0);

    float4 b = ((const float4*)bias)[lane];
    float4 acc;
    acc.x = acc0.x + acc1.x + b.x;
    acc.y = acc0.y + acc1.y + b.y;
    acc.z = acc0.z + acc1.z + b.z;
    acc.w = acc0.w + acc1.w + b.w;
    ((float4*)out)[(size_t)rowid * 32 + lane] = acc;
}

// ---------------------------------------------------------------- launch (fork/join streams for overlap)
extern "C" void kernel_launch(void* const* d_in, const int* in_sizes, int n_in,
                              void* d_out, int out_size) {
    const int*   row  = (const int*)d_in[0];
    const int*   col  = (const int*)d_in[1];
    const float* vals = (const float*)d_in[2];
    const float* feat = (const float*)d_in[3];
    const float* w    = (const float*)d_in[4];
    const float* bias = (const float*)d_in[5];
    float* out = (float*)d_out;

    int e = in_sizes[0];
    int n = in_sizes[3] / D;
    if (e > EMAX) e = EMAX;
    if (n > NMAX) n = NMAX;

    const int smemB = (128 + AROWS) * LDH * 2;   // 52224 B

    static cudaStream_t s1 = nullptr;
    static cudaEvent_t ev_fork = nullptr, ev_join = nullptr;
    if (s1 == nullptr) {
        cudaStreamCreateWithFlags(&s1, cudaStreamNonBlocking);
        cudaEventCreateWithFlags(&ev_fork, cudaEventDisableTiming);
        cudaEventCreateWithFlags(&ev_join, cudaEventDisableTiming);
        cudaFuncSetAttribute(k_gemm, cudaFuncAttributeMaxDynamicSharedMemorySize, smemB);
    }

    // fork: gemm on s1, scatter on main stream, both start immediately
    cudaEventRecord(ev_fork, 0);
    cudaStreamWaitEvent(s1, ev_fork, 0);
    k_gemm<<<(n + AROWS - 1) / AROWS, 256, smemB, s1>>>(feat, w, n);

    int nq = e >> 2;
    int half = (nq + 1) >> 1;
    k_scatter<<<(half + 255) / 256, 256>>>(row, col, vals, e);

    // join: gather needs scatter (stream order) and gemm (event)
    cudaEventRecord(ev_join, s1);
    cudaStreamWaitEvent(0, ev_join, 0);
    k_gather<<<(n * 32 + 255) / 256, 256>>>(bias, out, n);
}

// round 12
// speedup vs baseline: 1.8590x; 1.8590x over previous
#include <cuda_runtime.h>
#include <cuda_fp16.h>
#include <mma.h>

using namespace nvcuda;

#define NMAX 50000
#define EMAX 1600000
#define D 128
#define CAP 128          // slots per row (Poisson(32): P(>128) ~ 0)
#define LDH 136          // padded smem leading dim for fp16 tiles (halves)
#define LDS 132          // padded smem leading dim for fp32 staging (floats)
#define AROWS 64         // A-tile rows per block

// Scratch (static device globals — no allocation anywhere)
__device__ int      g_cnt[NMAX];
__device__ unsigned g_edge[(size_t)NMAX * CAP];   // packed: col (lo16) | fp16 val (hi16)
__device__ uint2    g_xwh[(size_t)NMAX * 32];     // XW fp16, row = 32 uint2

__device__ __forceinline__ unsigned pack_edge(int c, float v) {
    return (unsigned)c | ((unsigned)__half_as_ushort(__float2half_rn(v)) << 16);
}

// mixed-precision FMA: f16*f16 + f32 -> f32
__device__ __forceinline__ void edge_fma(unsigned p, int lane, float4& acc) {
    unsigned short c16, v16;
    asm("mov.b32 {%0, %1}, %2;" : "=h"(c16), "=h"(v16) : "r"(p));
    uint2 xu = g_xwh[(size_t)c16 * 32 + lane];
    unsigned short h0, h1, h2, h3;
    asm("mov.b32 {%0, %1}, %2;" : "=h"(h0), "=h"(h1) : "r"(xu.x));
    asm("mov.b32 {%0, %1}, %2;" : "=h"(h2), "=h"(h3) : "r"(xu.y));
    asm("fma.rn.f32.f16 %0, %1, %2, %0;" : "+f"(acc.x) : "h"(v16), "h"(h0));
    asm("fma.rn.f32.f16 %0, %1, %2, %0;" : "+f"(acc.y) : "h"(v16), "h"(h1));
    asm("fma.rn.f32.f16 %0, %1, %2, %0;" : "+f"(acc.z) : "h"(v16), "h"(h2));
    asm("fma.rn.f32.f16 %0, %1, %2, %0;" : "+f"(acc.w) : "h"(v16), "h"(h3));
}

// ---------------------------------------------------------------- scatter, 2 quads (8 chains) per thread
__global__ void k_scatter(const int* __restrict__ row, const int* __restrict__ col,
                          const float* __restrict__ vals, int e) {
    int nq = e >> 2;
    int half = (nq + 1) >> 1;
    int i = blockIdx.x * blockDim.x + threadIdx.x;
    if (i < half) {
        int iB = i + half;
        bool hasB = iB < nq;
        int4   rA = ((const int4*)row)[i];
        int4   cA = ((const int4*)col)[i];
        float4 vA = ((const float4*)vals)[i];
        int4 rB, cB; float4 vB;
        if (hasB) {
            rB = ((const int4*)row)[iB];
            cB = ((const int4*)col)[iB];
            vB = ((const float4*)vals)[iB];
        }
        int pA0 = atomicAdd(&g_cnt[rA.x], 1);
        int pA1 = atomicAdd(&g_cnt[rA.y], 1);
        int pA2 = atomicAdd(&g_cnt[rA.z], 1);
        int pA3 = atomicAdd(&g_cnt[rA.w], 1);
        int pB0 = 0, pB1 = 0, pB2 = 0, pB3 = 0;
        if (hasB) {
            pB0 = atomicAdd(&g_cnt[rB.x], 1);
            pB1 = atomicAdd(&g_cnt[rB.y], 1);
            pB2 = atomicAdd(&g_cnt[rB.z], 1);
            pB3 = atomicAdd(&g_cnt[rB.w], 1);
        }
        if (pA0 < CAP) g_edge[(size_t)rA.x * CAP + pA0] = pack_edge(cA.x, vA.x);
        if (pA1 < CAP) g_edge[(size_t)rA.y * CAP + pA1] = pack_edge(cA.y, vA.y);
        if (pA2 < CAP) g_edge[(size_t)rA.z * CAP + pA2] = pack_edge(cA.z, vA.z);
        if (pA3 < CAP) g_edge[(size_t)rA.w * CAP + pA3] = pack_edge(cA.w, vA.w);
        if (hasB) {
            if (pB0 < CAP) g_edge[(size_t)rB.x * CAP + pB0] = pack_edge(cB.x, vB.x);
            if (pB1 < CAP) g_edge[(size_t)rB.y * CAP + pB1] = pack_edge(cB.y, vB.y);
            if (pB2 < CAP) g_edge[(size_t)rB.z * CAP + pB2] = pack_edge(cB.z, vB.z);
            if (pB3 < CAP) g_edge[(size_t)rB.w * CAP + pB3] = pack_edge(cB.w, vB.w);
        }
    }
    if (i == 0) {
        for (int j = (e >> 2) << 2; j < e; j++) {
            int p = atomicAdd(&g_cnt[row[j]], 1);
            if (p < CAP) g_edge[(size_t)row[j] * CAP + p] = pack_edge(col[j], vals[j]);
        }
    }
}

// ---------------------------------------------------------------- XW = feat @ W (fp16 HMMA, fp32 accum)
// 64x128 tile per block, 256 threads = 8 warps (4x2), warp tile 16x64.
__global__ void __launch_bounds__(256, 3)
k_gemm(const float* __restrict__ feat, const float* __restrict__ w, int n) {
    extern __shared__ __align__(16) char smemraw[];
    __half* Ws = (__half*)smemraw;                    // [128][136] fp16 = 34.8 KB
    __half* As = Ws + 128 * LDH;                      // [64][136]  fp16 = 17.4 KB
    float*  St = (float*)smemraw;                     // fp32 staging [64][132] (reuse)
    int tid = threadIdx.x;

    const float4* w4 = (const float4*)w;
    for (int idx = tid; idx < D * 32; idx += 256) {
        int r = idx >> 5, q = idx & 31;
        float4 v = w4[idx];
        __half2 h0 = __floats2half2_rn(v.x, v.y);
        __half2 h1 = __floats2half2_rn(v.z, v.w);
        *(__half2*)(Ws + r * LDH + q * 4)     = h0;
        *(__half2*)(Ws + r * LDH + q * 4 + 2) = h1;
    }

    int rowBase = blockIdx.x * AROWS;
    const float4* f4 = (const float4*)feat;
    float4 z = make_float4(0.f, 0.f, 0.f, 0.f);
    for (int idx = tid; idx < AROWS * 32; idx += 256) {
        int r = idx >> 5, q = idx & 31;
        int gr = rowBase + r;
        float4 v = (gr < n) ? f4[(size_t)gr * 32 + q] : z;
        __half2 h0 = __floats2half2_rn(v.x, v.y);
        __half2 h1 = __floats2half2_rn(v.z, v.w);
        *(__half2*)(As + r * LDH + q * 4)     = h0;
        *(__half2*)(As + r * LDH + q * 4 + 2) = h1;
    }
    __syncthreads();

    int wid = tid >> 5;
    int wm = wid >> 1;     // 0..3 -> rows wm*16
    int wn = wid & 1;      // 0..1 -> cols wn*64

    wmma::fragment<wmma::accumulator, 16, 16, 16, float> acc[4];
#pragma unroll
    for (int j = 0; j < 4; j++) wmma::fill_fragment(acc[j], 0.f);

#pragma unroll
    for (int k0 = 0; k0 < D; k0 += 16) {
        wmma::fragment<wmma::matrix_a, 16, 16, 16, __half, wmma::row_major> a;
        wmma::fragment<wmma::matrix_b, 16, 16, 16, __half, wmma::row_major> b[4];
        wmma::load_matrix_sync(a, As + (wm * 16) * LDH + k0, LDH);
#pragma unroll
        for (int j = 0; j < 4; j++)
            wmma::load_matrix_sync(b[j], Ws + k0 * LDH + wn * 64 + j * 16, LDH);
#pragma unroll
        for (int j = 0; j < 4; j++)
            wmma::mma_sync(acc[j], a, b[j], acc[j]);
    }
    __syncthreads();   // done with fp16 tiles -> reuse smem as fp32 staging

#pragma unroll
    for (int j = 0; j < 4; j++)
        wmma::store_matrix_sync(St + (wm * 16) * LDS + wn * 64 + j * 16,
                                acc[j], LDS, wmma::mem_row_major);
    __syncthreads();

    for (int idx = tid; idx < AROWS * 32; idx += 256) {
        int r = idx >> 5, q = idx & 31;
        int gr = rowBase + r;
        if (gr < n) {
            float4 v = *(float4*)(St + r * LDS + q * 4);
            __half2 h0 = __floats2half2_rn(v.x, v.y);
            __half2 h1 = __floats2half2_rn(v.z, v.w);
            uint2 u;
            u.x = *reinterpret_cast<unsigned*>(&h0);
            u.y = *reinterpret_cast<unsigned*>(&h1);
            g_xwh[(size_t)gr * 32 + q] = u;
        }
    }
}

// ---------------------------------------------------------------- gather (dual accumulators)
__global__ void k_gather(const float* __restrict__ bias, float* __restrict__ out, int n) {
    int rowid = (blockIdx.x * blockDim.x + threadIdx.x) >> 5;
    int lane = threadIdx.x & 31;
    if (rowid >= n) return;

    int deg = g_cnt[rowid];
    if (deg > CAP) deg = CAP;
    const uint4* eb4 = (const uint4*)&g_edge[(size_t)rowid * CAP];

    float4 acc0 = make_float4(0.f, 0.f, 0.f, 0.f);
    float4 acc1 = make_float4(0.f, 0.f, 0.f, 0.f);

    int j = 0;
    for (; j + 8 <= deg; j += 8) {
        uint4 q0 = eb4[(j >> 2) + 0];
        uint4 q1 = eb4[(j >> 2) + 1];
        edge_fma(q0.x, lane, acc0);
        edge_fma(q0.y, lane, acc1);
        edge_fma(q0.z, lane, acc0);
        edge_fma(q0.w, lane, acc1);
        edge_fma(q1.x, lane, acc0);
        edge_fma(q1.y, lane, acc1);
        edge_fma(q1.z, lane, acc0);
        edge_fma(q1.w, lane, acc1);
    }
    if (j + 4 <= deg) {
        uint4 q0 = eb4[j >> 2];
        edge_fma(q0.x, lane, acc0);
        edge_fma(q0.y, lane, acc1);
        edge_fma(q0.z, lane, acc0);
        edge_fma(q0.w, lane, acc1);
        j += 4;
    }
    const unsigned* eb = &g_edge[(size_t)rowid * CAP];
    for (; j < deg; j++) edge_fma(eb[j], lane, acc0);

    float4 b = ((const float4*)bias)[lane];
    float4 acc;
    acc.x = acc0.x + acc1.x + b.x;
    acc.y = acc0.y + acc1.y + b.y;
    acc.z = acc0.z + acc1.z + b.z;
    acc.w = acc0.w + acc1.w + b.w;
    ((float4*)out)[(size_t)rowid * 32 + lane] = acc;
}

// ---------------------------------------------------------------- launch (fork/join streams for overlap)
extern "C" void kernel_launch(void* const* d_in, const int* in_sizes, int n_in,
                              void* d_out, int out_size) {
    const int*   row  = (const int*)d_in[0];
    const int*   col  = (const int*)d_in[1];
    const float* vals = (const float*)d_in[2];
    const float* feat = (const float*)d_in[3];
    const float* w    = (const float*)d_in[4];
    const float* bias = (const float*)d_in[5];
    float* out = (float*)d_out;

    int e = in_sizes[0];
    int n = in_sizes[3] / D;
    if (e > EMAX) e = EMAX;
    if (n > NMAX) n = NMAX;

    const int smemB = (128 + AROWS) * LDH * 2;   // 52224 B

    static cudaStream_t s1 = nullptr;
    static cudaEvent_t ev_fork = nullptr, ev_join = nullptr;
    if (s1 == nullptr) {
        cudaStreamCreateWithFlags(&s1, cudaStreamNonBlocking);
        cudaEventCreateWithFlags(&ev_fork, cudaEventDisableTiming);
        cudaEventCreateWithFlags(&ev_join, cudaEventDisableTiming);
        cudaFuncSetAttribute(k_gemm, cudaFuncAttributeMaxDynamicSharedMemorySize, smemB);
    }

    // fork FIRST: gemm is independent of g_cnt memset + scatter
    cudaEventRecord(ev_fork, 0);
    cudaStreamWaitEvent(s1, ev_fork, 0);
    k_gemm<<<(n + AROWS - 1) / AROWS, 256, smemB, s1>>>(feat, w, n);

    void* pcnt = nullptr;
    cudaGetSymbolAddress(&pcnt, g_cnt);
    cudaMemsetAsync(pcnt, 0, (size_t)n * sizeof(int), 0);

    int nq = e >> 2;
    int half = (nq + 1) >> 1;
    k_scatter<<<(half + 255) / 256, 256>>>(row, col, vals, e);

    // join: gather needs scatter (stream order) and gemm (event)
    cudaEventRecord(ev_join, s1);
    cudaStreamWaitEvent(0, ev_join, 0);
    k_gather<<<(n * 32 + 255) / 256, 256>>>(bias, out, n);
}

// round 13
// speedup vs baseline: 1.8872x; 1.0152x over previous
#include <cuda_runtime.h>
#include <cuda_fp16.h>
#include <mma.h>

using namespace nvcuda;

#define NMAX 50000
#define EMAX 1600000
#define D 128
#define CAP 128          // slots per row (Poisson(32): P(>128) ~ 0)
#define LDH 136          // padded smem leading dim for fp16 tiles (halves)
#define LDS 132          // padded smem leading dim for fp32 staging (floats)
#define AROWS 64         // A-tile rows per block

// Scratch (static device globals — no allocation anywhere)
__device__ int      g_cnt[NMAX];
__device__ unsigned g_edge[(size_t)NMAX * CAP];   // packed: col (lo16) | fp16 val (hi16)
__device__ uint2    g_xwh[(size_t)NMAX * 32];     // XW fp16, row = 32 uint2

__device__ __forceinline__ unsigned pack_edge(int c, float v) {
    return (unsigned)c | ((unsigned)__half_as_ushort(__float2half_rn(v)) << 16);
}

// mixed-precision FMA: f16*f16 + f32 -> f32
__device__ __forceinline__ void edge_fma(unsigned p, int lane, float4& acc) {
    unsigned short c16, v16;
    asm("mov.b32 {%0, %1}, %2;" : "=h"(c16), "=h"(v16) : "r"(p));
    uint2 xu = g_xwh[(size_t)c16 * 32 + lane];
    unsigned short h0, h1, h2, h3;
    asm("mov.b32 {%0, %1}, %2;" : "=h"(h0), "=h"(h1) : "r"(xu.x));
    asm("mov.b32 {%0, %1}, %2;" : "=h"(h2), "=h"(h3) : "r"(xu.y));
    asm("fma.rn.f32.f16 %0, %1, %2, %0;" : "+f"(acc.x) : "h"(v16), "h"(h0));
    asm("fma.rn.f32.f16 %0, %1, %2, %0;" : "+f"(acc.y) : "h"(v16), "h"(h1));
    asm("fma.rn.f32.f16 %0, %1, %2, %0;" : "+f"(acc.z) : "h"(v16), "h"(h2));
    asm("fma.rn.f32.f16 %0, %1, %2, %0;" : "+f"(acc.w) : "h"(v16), "h"(h3));
}

// ---------------------------------------------------------------- scatter, 2 quads (8 chains) per thread
__global__ void k_scatter(const int* __restrict__ row, const int* __restrict__ col,
                          const float* __restrict__ vals, int e) {
    int nq = e >> 2;
    int half = (nq + 1) >> 1;
    int i = blockIdx.x * blockDim.x + threadIdx.x;
    if (i < half) {
        int iB = i + half;
        bool hasB = iB < nq;
        int4   rA = ((const int4*)row)[i];
        int4   cA = ((const int4*)col)[i];
        float4 vA = ((const float4*)vals)[i];
        int4 rB, cB; float4 vB;
        if (hasB) {
            rB = ((const int4*)row)[iB];
            cB = ((const int4*)col)[iB];
            vB = ((const float4*)vals)[iB];
        }
        int pA0 = atomicAdd(&g_cnt[rA.x], 1);
        int pA1 = atomicAdd(&g_cnt[rA.y], 1);
        int pA2 = atomicAdd(&g_cnt[rA.z], 1);
        int pA3 = atomicAdd(&g_cnt[rA.w], 1);
        int pB0 = 0, pB1 = 0, pB2 = 0, pB3 = 0;
        if (hasB) {
            pB0 = atomicAdd(&g_cnt[rB.x], 1);
            pB1 = atomicAdd(&g_cnt[rB.y], 1);
            pB2 = atomicAdd(&g_cnt[rB.z], 1);
            pB3 = atomicAdd(&g_cnt[rB.w], 1);
        }
        if (pA0 < CAP) g_edge[(size_t)rA.x * CAP + pA0] = pack_edge(cA.x, vA.x);
        if (pA1 < CAP) g_edge[(size_t)rA.y * CAP + pA1] = pack_edge(cA.y, vA.y);
        if (pA2 < CAP) g_edge[(size_t)rA.z * CAP + pA2] = pack_edge(cA.z, vA.z);
        if (pA3 < CAP) g_edge[(size_t)rA.w * CAP + pA3] = pack_edge(cA.w, vA.w);
        if (hasB) {
            if (pB0 < CAP) g_edge[(size_t)rB.x * CAP + pB0] = pack_edge(cB.x, vB.x);
            if (pB1 < CAP) g_edge[(size_t)rB.y * CAP + pB1] = pack_edge(cB.y, vB.y);
            if (pB2 < CAP) g_edge[(size_t)rB.z * CAP + pB2] = pack_edge(cB.z, vB.z);
            if (pB3 < CAP) g_edge[(size_t)rB.w * CAP + pB3] = pack_edge(cB.w, vB.w);
        }
    }
    if (i == 0) {
        for (int j = (e >> 2) << 2; j < e; j++) {
            int p = atomicAdd(&g_cnt[row[j]], 1);
            if (p < CAP) g_edge[(size_t)row[j] * CAP + p] = pack_edge(col[j], vals[j]);
        }
    }
}

// ---------------------------------------------------------------- XW = feat @ W (fp16 HMMA, fp32 accum)
// 64x128 tile per block, 256 threads = 8 warps (4x2), warp tile 16x64.
__global__ void __launch_bounds__(256, 3)
k_gemm(const float* __restrict__ feat, const float* __restrict__ w, int n) {
    extern __shared__ __align__(16) char smemraw[];
    __half* Ws = (__half*)smemraw;                    // [128][136] fp16 = 34.8 KB
    __half* As = Ws + 128 * LDH;                      // [64][136]  fp16 = 17.4 KB
    float*  St = (float*)smemraw;                     // fp32 staging [64][132] (reuse)
    int tid = threadIdx.x;

    const float4* w4 = (const float4*)w;
    for (int idx = tid; idx < D * 32; idx += 256) {
        int r = idx >> 5, q = idx & 31;
        float4 v = w4[idx];
        __half2 h0 = __floats2half2_rn(v.x, v.y);
        __half2 h1 = __floats2half2_rn(v.z, v.w);
        *(__half2*)(Ws + r * LDH + q * 4)     = h0;
        *(__half2*)(Ws + r * LDH + q * 4 + 2) = h1;
    }

    int rowBase = blockIdx.x * AROWS;
    const float4* f4 = (const float4*)feat;
    float4 z = make_float4(0.f, 0.f, 0.f, 0.f);
    for (int idx = tid; idx < AROWS * 32; idx += 256) {
        int r = idx >> 5, q = idx & 31;
        int gr = rowBase + r;
        float4 v = (gr < n) ? f4[(size_t)gr * 32 + q] : z;
        __half2 h0 = __floats2half2_rn(v.x, v.y);
        __half2 h1 = __floats2half2_rn(v.z, v.w);
        *(__half2*)(As + r * LDH + q * 4)     = h0;
        *(__half2*)(As + r * LDH + q * 4 + 2) = h1;
    }
    __syncthreads();

    int wid = tid >> 5;
    int wm = wid >> 1;     // 0..3 -> rows wm*16
    int wn = wid & 1;      // 0..1 -> cols wn*64

    wmma::fragment<wmma::accumulator, 16, 16, 16, float> acc[4];
#pragma unroll
    for (int j = 0; j < 4; j++) wmma::fill_fragment(acc[j], 0.f);

#pragma unroll
    for (int k0 = 0; k0 < D; k0 += 16) {
        wmma::fragment<wmma::matrix_a, 16, 16, 16, __half, wmma::row_major> a;
        wmma::fragment<wmma::matrix_b, 16, 16, 16, __half, wmma::row_major> b[4];
        wmma::load_matrix_sync(a, As + (wm * 16) * LDH + k0, LDH);
#pragma unroll
        for (int j = 0; j < 4; j++)
            wmma::load_matrix_sync(b[j], Ws + k0 * LDH + wn * 64 + j * 16, LDH);
#pragma unroll
        for (int j = 0; j < 4; j++)
            wmma::mma_sync(acc[j], a, b[j], acc[j]);
    }
    __syncthreads();   // done with fp16 tiles -> reuse smem as fp32 staging

#pragma unroll
    for (int j = 0; j < 4; j++)
        wmma::store_matrix_sync(St + (wm * 16) * LDS + wn * 64 + j * 16,
                                acc[j], LDS, wmma::mem_row_major);
    __syncthreads();

    for (int idx = tid; idx < AROWS * 32; idx += 256) {
        int r = idx >> 5, q = idx & 31;
        int gr = rowBase + r;
        if (gr < n) {
            float4 v = *(float4*)(St + r * LDS + q * 4);
            __half2 h0 = __floats2half2_rn(v.x, v.y);
            __half2 h1 = __floats2half2_rn(v.z, v.w);
            uint2 u;
            u.x = *reinterpret_cast<unsigned*>(&h0);
            u.y = *reinterpret_cast<unsigned*>(&h1);
            g_xwh[(size_t)gr * 32 + q] = u;
        }
    }
}

// ---------------------------------------------------------------- gather (dual accumulators)
__global__ void k_gather(const float* __restrict__ bias, float* __restrict__ out, int n) {
    int rowid = (blockIdx.x * blockDim.x + threadIdx.x) >> 5;
    int lane = threadIdx.x & 31;
    if (rowid >= n) return;

    int deg = g_cnt[rowid];
    if (deg > CAP) deg = CAP;
    const uint4* eb4 = (const uint4*)&g_edge[(size_t)rowid * CAP];

    float4 acc0 = make_float4(0.f, 0.f, 0.f, 0.f);
    float4 acc1 = make_float4(0.f, 0.f, 0.f, 0.f);

    int j = 0;
    for (; j + 8 <= deg; j += 8) {
        uint4 q0 = eb4[(j >> 2) + 0];
        uint4 q1 = eb4[(j >> 2) + 1];
        edge_fma(q0.x, lane, acc0);
        edge_fma(q0.y, lane, acc1);
        edge_fma(q0.z, lane, acc0);
        edge_fma(q0.w, lane, acc1);
        edge_fma(q1.x, lane, acc0);
        edge_fma(q1.y, lane, acc1);
        edge_fma(q1.z, lane, acc0);
        edge_fma(q1.w, lane, acc1);
    }
    if (j + 4 <= deg) {
        uint4 q0 = eb4[j >> 2];
        edge_fma(q0.x, lane, acc0);
        edge_fma(q0.y, lane, acc1);
        edge_fma(q0.z, lane, acc0);
        edge_fma(q0.w, lane, acc1);
        j += 4;
    }
    const unsigned* eb = &g_edge[(size_t)rowid * CAP];
    for (; j < deg; j++) edge_fma(eb[j], lane, acc0);

    float4 b = ((const float4*)bias)[lane];
    float4 acc;
    acc.x = acc0.x + acc1.x + b.x;
    acc.y = acc0.y + acc1.y + b.y;
    acc.z = acc0.z + acc1.z + b.z;
    acc.w = acc0.w + acc1.w + b.w;
    ((float4*)out)[(size_t)rowid * 32 + lane] = acc;
}

// ---------------------------------------------------------------- launch (3-stream fork/join)
extern "C" void kernel_launch(void* const* d_in, const int* in_sizes, int n_in,
                              void* d_out, int out_size) {
    const int*   row  = (const int*)d_in[0];
    const int*   col  = (const int*)d_in[1];
    const float* vals = (const float*)d_in[2];
    const float* feat = (const float*)d_in[3];
    const float* w    = (const float*)d_in[4];
    const float* bias = (const float*)d_in[5];
    float* out = (float*)d_out;

    int e = in_sizes[0];
    int n = in_sizes[3] / D;
    if (e > EMAX) e = EMAX;
    if (n > NMAX) n = NMAX;

    const int smemB = (128 + AROWS) * LDH * 2;   // 52224 B

    static cudaStream_t s1 = nullptr, s2 = nullptr;
    static cudaEvent_t ev_fork = nullptr, ev_join = nullptr, ev_m = nullptr;
    if (s1 == nullptr) {
        cudaStreamCreateWithFlags(&s1, cudaStreamNonBlocking);
        cudaStreamCreateWithFlags(&s2, cudaStreamNonBlocking);
        cudaEventCreateWithFlags(&ev_fork, cudaEventDisableTiming);
        cudaEventCreateWithFlags(&ev_join, cudaEventDisableTiming);
        cudaEventCreateWithFlags(&ev_m, cudaEventDisableTiming);
        cudaFuncSetAttribute(k_gemm, cudaFuncAttributeMaxDynamicSharedMemorySize, smemB);
    }

    // fork: gemm on s1, memset on s2, scatter on main (after memset event)
    cudaEventRecord(ev_fork, 0);
    cudaStreamWaitEvent(s1, ev_fork, 0);
    k_gemm<<<(n + AROWS - 1) / AROWS, 256, smemB, s1>>>(feat, w, n);

    cudaStreamWaitEvent(s2, ev_fork, 0);
    void* pcnt = nullptr;
    cudaGetSymbolAddress(&pcnt, g_cnt);
    cudaMemsetAsync(pcnt, 0, (size_t)n * sizeof(int), s2);
    cudaEventRecord(ev_m, s2);

    cudaStreamWaitEvent(0, ev_m, 0);
    int nq = e >> 2;
    int half = (nq + 1) >> 1;
    k_scatter<<<(half + 255) / 256, 256>>>(row, col, vals, e);

    // join: gather needs scatter (stream order) and gemm (event)
    cudaEventRecord(ev_join, s1);
    cudaStreamWaitEvent(0, ev_join, 0);
    k_gather<<<(n * 32 + 255) / 256, 256>>>(bias, out, n);
}